// round 14
// baseline (speedup 1.0000x reference)
#include <cuda_runtime.h>
#include <cuda_bf16.h>
#include <cuda_fp8.h>
#include <cuda_fp16.h>
#include <math.h>
#include <stdint.h>

// Problem shape (fixed)
#define T 1024
#define H 2880
#define NI 2880
#define NEXP 8
#define R1 5760          // 2*I rows of gate_up
#define G 90             // K groups of 32
#define NA 2048          // T * topk

// GEMM tile: C[128,128], K-step 64 (two fp4 groups) per iteration.
// 8 warps of 32x64 (4 M-slots x 2 N-slots).
#define BM 128
#define BN 128
#define BK 64
#define CHUNKS 45                    // 2880 / 64
#define ASTRB 144                    // padded row stride bytes (128B + 16B pad)
#define A_BYTES (BM * ASTRB)         // 18432
#define B_BYTES (BN * ASTRB)         // 18432
#define STAGE_B (A_BYTES + B_BYTES)  // 36864
#define SMEM_DYN (1024 + 2 * STAGE_B)

// ---------------- scratch ---------------------------------------------------
__device__ __nv_bfloat16 g_xq[T * H];      // qdq'd hidden, bf16 (exact)
__device__ __nv_bfloat16 g_actb[NA * NI];  // qdq'd activations, bf16 (exact)
__device__ float         g_out2[NA * H];   // per-assignment outputs
__device__ int g_tok[NA], g_pair_row[NA], g_cnt[NEXP], g_off[NEXP];

// ---------------- expert grouping (deterministic) ---------------------------
__global__ void build_lists_kernel(const int* __restrict__ eidx) {
    __shared__ int se[NA];
    __shared__ int offs[NEXP];
    int tid = threadIdx.x;
    for (int i = tid; i < NA; i += 256) se[i] = eidx[i];
    __syncthreads();
    if (tid < NEXP) {
        int c = 0;
        for (int i = 0; i < NA; i++) c += (se[i] == tid);
        g_cnt[tid] = c;
    }
    __syncthreads();
    if (tid == 0) {
        int s = 0;
        for (int e = 0; e < NEXP; e++) { offs[e] = s; g_off[e] = s; s += g_cnt[e]; }
    }
    __syncthreads();
    if (tid < NEXP) {
        int pos = offs[tid];
        for (int i = 0; i < NA; i++) {
            if (se[i] == tid) {
                g_tok[pos] = i >> 1;
                g_pair_row[i] = pos;
                pos++;
            }
        }
    }
}

// ---------------- MXFP8 qdq helpers ------------------------------------------
__device__ __forceinline__ int ceil_log2(float a) {
    int k; float m = frexpf(a, &k);
    int ee = (m == 0.5f) ? (k - 1) : k;   // exact ceil(log2(a))
    return max(-127, min(128, ee));
}
__device__ __forceinline__ float qdq_one(float v, float inv, float scale) {
    __nv_fp8_storage_t q = __nv_cvt_float_to_fp8(v * inv, __NV_SATFINITE, __NV_E4M3);
    __half_raw hr = __nv_cvt_fp8_to_halfraw(q, __NV_E4M3);
    return __half2float(*(__half*)&hr) * scale;
}

// Vectorized hidden qdq: 8 values/thread, 4 threads per 32-block.
__global__ void qdq_hidden_kernel(const float* __restrict__ in) {
    int gid = blockIdx.x * blockDim.x + threadIdx.x;   // T*H/8 threads
    size_t idx = (size_t)gid * 8;
    float4 v0 = *(const float4*)(in + idx);
    float4 v1 = *(const float4*)(in + idx + 4);
    float f[8] = {v0.x, v0.y, v0.z, v0.w, v1.x, v1.y, v1.z, v1.w};
    float a = 0.0f;
#pragma unroll
    for (int j = 0; j < 8; j++) a = fmaxf(a, fabsf(f[j]));
    a = fmaxf(a, __shfl_xor_sync(0xffffffffu, a, 1));
    a = fmaxf(a, __shfl_xor_sync(0xffffffffu, a, 2));
    a = fmaxf(a, 1e-12f);
    int ee = ceil_log2(a);
    float inv = ldexpf(1.0f, -ee);
    float scale = ldexpf(1.0f, ee);
    __nv_bfloat16 o[8];
#pragma unroll
    for (int j = 0; j < 8; j++) o[j] = __float2bfloat16(qdq_one(f[j], inv, scale));
    *(uint4*)(g_xq + idx) = *(uint4*)o;
}

// ---------------- low-level helpers -----------------------------------------
__device__ __forceinline__ void ldsm_x4(uint32_t* r, uint32_t addr) {
    asm volatile("ldmatrix.sync.aligned.m8n8.x4.shared.b16 {%0,%1,%2,%3}, [%4];\n"
                 : "=r"(r[0]), "=r"(r[1]), "=r"(r[2]), "=r"(r[3]) : "r"(addr));
}
__device__ __forceinline__ void mma16816(float* d, const uint32_t* a,
                                         uint32_t b0, uint32_t b1) {
    asm volatile(
        "mma.sync.aligned.m16n8k16.row.col.f32.bf16.bf16.f32 "
        "{%0,%1,%2,%3}, {%4,%5,%6,%7}, {%8,%9}, {%0,%1,%2,%3};\n"
        : "+f"(d[0]), "+f"(d[1]), "+f"(d[2]), "+f"(d[3])
        : "r"(a[0]), "r"(a[1]), "r"(a[2]), "r"(a[3]), "r"(b0), "r"(b1));
}
__device__ __forceinline__ void cp16(uint32_t dst, const void* src) {
    asm volatile("cp.async.cg.shared.global [%0], [%1], 16;\n"
                 :: "r"(dst), "l"(src));
}
__device__ __forceinline__ uint32_t mulbf2(uint32_t a, uint32_t b) {
    uint32_t d;
    asm("mul.rn.bf16x2 %0, %1, %2;\n" : "=r"(d) : "r"(a), "r"(b));
    return d;
}

// PRMT-based fp4 dequant (verified R10-R13): 4 int32 (one packed byte each) +
// E8M0 scale -> 4 x bf16x2 in k-order. Exact in bf16.
__device__ __forceinline__ void dequant8(int4 v, int sval, uint32_t* out) {
    uint32_t c1 = __byte_perm((uint32_t)v.x, (uint32_t)v.y, 0x0040);
    uint32_t c2 = __byte_perm((uint32_t)v.z, (uint32_t)v.w, 0x4000);
    uint32_t comb = __byte_perm(c1, c2, 0x7610);   // [b(x),b(y),b(z),b(w)]
    uint32_t chn = comb >> 4;
    uint32_t xl = comb & 0x07070707u;
    uint32_t xh = chn & 0x07070707u;
    uint32_t sgl = (comb & 0x08080808u) << 4;
    uint32_t sgh = (chn & 0x08080808u) << 4;
    uint32_t yl = xl | (xl >> 4);
    uint32_t yh = xh | (xh >> 4);
    uint32_t sel_l = __byte_perm(yl, yl, 0x0020);
    uint32_t sel_h = __byte_perm(yh, yh, 0x0020);
    uint32_t hbLo = __byte_perm(0x3F3F3F00u, 0x40404040u, sel_l) | sgl;
    uint32_t lbLo = __byte_perm(0xC0800000u, 0xC0804000u, sel_l);
    uint32_t hbHi = __byte_perm(0x3F3F3F00u, 0x40404040u, sel_h) | sgh;
    uint32_t lbHi = __byte_perm(0xC0800000u, 0xC0804000u, sel_h);
    uint32_t M0 = __byte_perm(lbLo, hbLo, 0x5140);
    uint32_t M1 = __byte_perm(lbLo, hbLo, 0x7362);
    uint32_t N0 = __byte_perm(lbHi, hbHi, 0x5140);
    uint32_t N1 = __byte_perm(lbHi, hbHi, 0x7362);
    uint32_t sb = ((uint32_t)sval) << 7;
    sb |= sb << 16;
    out[0] = mulbf2(__byte_perm(M0, N0, 0x5410), sb);
    out[1] = mulbf2(__byte_perm(M0, N0, 0x7632), sb);
    out[2] = mulbf2(__byte_perm(M1, N1, 0x5410), sb);
    out[3] = mulbf2(__byte_perm(M1, N1, 0x7632), sb);
}

// ---------------- tensor-core GEMM (both stages) -----------------------------
// C[128,128] per block; 8 warps of 32x64; K loop over 45 chunks of 64.
// 2-stage smem double buffer. A staged via cp.async (issued just after the
// barrier into the proven-free stage; waited one full compute phase later).
// B raw int32 via LDG register prefetch + PRMT dequant. One barrier per chunk.
// GEMM1 fuses swiglu + act MXFP8-qdq (one 32-col qdq block per warp, no
// cross-warp exchange).
template <bool IS_G1>
__global__ __launch_bounds__(256, 2) void gemm_mma_kernel(
    const int* __restrict__ wblocks, const int* __restrict__ wscales,
    const float* __restrict__ wbias, int NR) {
    extern __shared__ char dsmem[];
    int e = blockIdx.z;
    int cnt = g_cnt[e];
    int m0 = blockIdx.y * BM;
    if (m0 >= cnt) return;
    int off = g_off[e];
    int nt = blockIdx.x;
    int tid = threadIdx.x;

    uint32_t sbase = (uint32_t)__cvta_generic_to_shared(dsmem);
    uint32_t abase = (sbase + 1023) & ~1023u;
    uint32_t st_u[2] = {abase, abase + STAGE_B};

    // --- A mapping: 2 threads per row, 64B (32 bf16) each, via cp.async ---
    int a_m = tid >> 1;
    int a_half = tid & 1;
    int arow = min(m0 + a_m, cnt - 1);   // clamp; garbage rows never stored out
    const __nv_bfloat16* aptr;
    if (IS_G1) {
        aptr = g_xq + (size_t)g_tok[off + arow] * H + a_half * 32;
    } else {
        aptr = g_actb + (size_t)(off + arow) * NI + a_half * 32;
    }
    // --- B mapping: 2 threads per weight row; each owns one k32-group/chunk ---
    int b_n = tid >> 1;
    int b_half = tid & 1;
    int wr = min(nt * BN + b_n, NR - 1);         // clamp for GEMM2 tail block
    size_t wrow = (size_t)e * NR + wr;
    const int* bptr = wblocks + wrow * (G * 16);
    const int* sptr = wscales + wrow * G;

    uint32_t a_dst = (uint32_t)a_m * ASTRB + a_half * 64;            // bytes
    uint32_t b_dst = A_BYTES + (uint32_t)b_n * ASTRB + b_half * 64;

    // per-warp ldmatrix offsets (within a stage)
    int wid = tid >> 5, lane = tid & 31;
    int wm = (wid & 3) * 32;
    int wn = (wid >> 2) * 64;
    uint32_t aA_off = (uint32_t)(wm + (lane & 15)) * ASTRB + (lane >> 4) * 16;
    uint32_t aB_off = A_BYTES + (uint32_t)(wn + (lane & 15)) * ASTRB +
                      (lane >> 4) * 16;

    float acc[2][8][4];
#pragma unroll
    for (int i = 0; i < 2; i++)
#pragma unroll
        for (int j = 0; j < 8; j++)
#pragma unroll
            for (int c = 0; c < 4; c++) acc[i][j][c] = 0.0f;

    // ---- prologue: A(0) via cp.async; B(0) via regs -> smem ----
    {
#pragma unroll
        for (int j = 0; j < 4; j++)
            cp16(st_u[0] + a_dst + j * 16, aptr + j * 8);
        asm volatile("cp.async.commit_group;\n");
        int4 bv[4];
#pragma unroll
        for (int j = 0; j < 4; j++) bv[j] = *(const int4*)(bptr + b_half * 16 + j * 4);
        int sv = sptr[b_half];
#pragma unroll
        for (int j = 0; j < 4; j++) {
            uint32_t o[4];
            dequant8(bv[j], sv, o);
            asm volatile("st.shared.v4.b32 [%0], {%1,%2,%3,%4};"
                         :: "r"(st_u[0] + b_dst + j * 16),
                            "r"(o[0]), "r"(o[1]), "r"(o[2]), "r"(o[3]));
        }
    }

    for (int c = 0; c < CHUNKS; ++c) {
        bool have_next = (c + 1 < CHUNKS);
        // B(c+1) raw loads (land during compute below)
        int4 bvn[4]; int svn = 0;
        if (have_next) {
            const int* bp = bptr + (size_t)(2 * (c + 1) + b_half) * 16;
#pragma unroll
            for (int j = 0; j < 4; j++) bvn[j] = *(const int4*)(bp + j * 4);
            svn = sptr[2 * (c + 1) + b_half];
        }
        // A(c) must have landed (only group in flight)
        asm volatile("cp.async.wait_group 0;\n");
        __syncthreads();   // stage c&1 fully visible; stage (c+1)&1 now free
        // issue A(c+1) into the just-freed stage
        if (have_next) {
            uint32_t d = st_u[(c + 1) & 1] + a_dst;
            const __nv_bfloat16* ap = aptr + (size_t)(c + 1) * BK;
#pragma unroll
            for (int j = 0; j < 4; j++) cp16(d + j * 16, ap + j * 8);
            asm volatile("cp.async.commit_group;\n");
        }
        // compute chunk c from stage c&1 (4 K16 steps, 32 HMMA/warp)
        uint32_t aA = st_u[c & 1] + aA_off;
        uint32_t aB = st_u[c & 1] + aB_off;
#pragma unroll
        for (int ss = 0; ss < 4; ss++) {
            uint32_t A0[4], A1[4], B0[4], B1[4], B2[4], B3[4];
            ldsm_x4(A0, aA + ss * 32);
            ldsm_x4(A1, aA + 16 * ASTRB + ss * 32);
            ldsm_x4(B0, aB + ss * 32);
            ldsm_x4(B1, aB + 16 * ASTRB + ss * 32);
            ldsm_x4(B2, aB + 32 * ASTRB + ss * 32);
            ldsm_x4(B3, aB + 48 * ASTRB + ss * 32);
            mma16816(acc[0][0], A0, B0[0], B0[2]);
            mma16816(acc[0][1], A0, B0[1], B0[3]);
            mma16816(acc[0][2], A0, B1[0], B1[2]);
            mma16816(acc[0][3], A0, B1[1], B1[3]);
            mma16816(acc[0][4], A0, B2[0], B2[2]);
            mma16816(acc[0][5], A0, B2[1], B2[3]);
            mma16816(acc[0][6], A0, B3[0], B3[2]);
            mma16816(acc[0][7], A0, B3[1], B3[3]);
            mma16816(acc[1][0], A1, B0[0], B0[2]);
            mma16816(acc[1][1], A1, B0[1], B0[3]);
            mma16816(acc[1][2], A1, B1[0], B1[2]);
            mma16816(acc[1][3], A1, B1[1], B1[3]);
            mma16816(acc[1][4], A1, B2[0], B2[2]);
            mma16816(acc[1][5], A1, B2[1], B2[3]);
            mma16816(acc[1][6], A1, B3[0], B3[2]);
            mma16816(acc[1][7], A1, B3[1], B3[3]);
        }
        // dequant + store B(c+1) into stage (c+1)&1 (readers done in iter c-1)
        if (have_next) {
            uint32_t d = st_u[(c + 1) & 1] + b_dst;
#pragma unroll
            for (int j = 0; j < 4; j++) {
                uint32_t o[4];
                dequant8(bvn[j], svn, o);
                asm volatile("st.shared.v4.b32 [%0], {%1,%2,%3,%4};"
                             :: "r"(d + j * 16),
                                "r"(o[0]), "r"(o[1]), "r"(o[2]), "r"(o[3]));
            }
        }
    }

    // ---------------- epilogue ----------------
    int lm = lane >> 2;
    int lc = (lane & 3) * 2;
    if (IS_G1) {
        // swiglu -> act; one 32-col qdq block per warp (64 h-cols), warp-local.
        float rmax[2][2] = {{0.f, 0.f}, {0.f, 0.f}};
#pragma unroll
        for (int mi = 0; mi < 2; mi++) {
#pragma unroll
            for (int nj = 0; nj < 8; nj++) {
                int col = nt * BN + wn + nj * 8 + lc;
                float be = wbias[e * R1 + col];
                float bo = wbias[e * R1 + col + 1];
                {
                    float gate = fminf(acc[mi][nj][0] + be, 7.0f);
                    float up = fminf(fmaxf(acc[mi][nj][1] + bo, -7.0f), 7.0f);
                    float glu = gate / (1.0f + expf(-1.702f * gate));
                    float a0 = (up + 1.0f) * glu;
                    acc[mi][nj][0] = a0;                 // reuse storage
                    rmax[mi][0] = fmaxf(rmax[mi][0], fabsf(a0));
                }
                {
                    float gate = fminf(acc[mi][nj][2] + be, 7.0f);
                    float up = fminf(fmaxf(acc[mi][nj][3] + bo, -7.0f), 7.0f);
                    float glu = gate / (1.0f + expf(-1.702f * gate));
                    float a1 = (up + 1.0f) * glu;
                    acc[mi][nj][2] = a1;
                    rmax[mi][1] = fmaxf(rmax[mi][1], fabsf(a1));
                }
            }
        }
#pragma unroll
        for (int mi = 0; mi < 2; mi++)
#pragma unroll
            for (int p = 0; p < 2; p++) {
                rmax[mi][p] = fmaxf(rmax[mi][p],
                                    __shfl_xor_sync(0xffffffffu, rmax[mi][p], 1));
                rmax[mi][p] = fmaxf(rmax[mi][p],
                                    __shfl_xor_sync(0xffffffffu, rmax[mi][p], 2));
            }
#pragma unroll
        for (int mi = 0; mi < 2; mi++) {
#pragma unroll
            for (int p = 0; p < 2; p++) {
                int rbase = m0 + wm + mi * 16 + p * 8 + lm;
                if (rbase < cnt) {
                    float bm = fmaxf(rmax[mi][p], 1e-12f);
                    int ee = ceil_log2(bm);
                    float inv = ldexpf(1.0f, -ee);
                    float scale = ldexpf(1.0f, ee);
                    __nv_bfloat16* dst = g_actb + (size_t)(off + rbase) * NI +
                                         nt * (BN / 2) + (wn >> 1) + (lane & 3);
#pragma unroll
                    for (int nj = 0; nj < 8; nj++)
                        dst[nj * 4] = __float2bfloat16(
                            qdq_one(acc[mi][nj][2 * p], inv, scale));
                }
            }
        }
    } else {
#pragma unroll
        for (int mi = 0; mi < 2; mi++) {
#pragma unroll
            for (int nj = 0; nj < 8; nj++) {
                int col = nt * BN + wn + nj * 8 + lc;
                if (col < NR) {
                    int rbase = m0 + wm + mi * 16 + lm;
                    float b0 = wbias[e * H + col];
                    float b1 = wbias[e * H + col + 1];
                    if (rbase < cnt) {
                        float2 r = make_float2(acc[mi][nj][0] + b0,
                                               acc[mi][nj][1] + b1);
                        *(float2*)(g_out2 + (size_t)(off + rbase) * H + col) = r;
                    }
                    if (rbase + 8 < cnt) {
                        float2 r = make_float2(acc[mi][nj][2] + b0,
                                               acc[mi][nj][3] + b1);
                        *(float2*)(g_out2 + (size_t)(off + rbase + 8) * H + col) = r;
                    }
                }
            }
        }
    }
}

// ---------------- combine (deterministic) -----------------------------------
__global__ void combine_kernel(const float* __restrict__ rw,
                               float* __restrict__ out) {
    int t = blockIdx.x;
    int r0 = g_pair_row[t * 2 + 0];
    int r1 = g_pair_row[t * 2 + 1];
    float w0 = rw[t * 2 + 0];
    float w1 = rw[t * 2 + 1];
    const float* p0 = g_out2 + (size_t)r0 * H;
    const float* p1 = g_out2 + (size_t)r1 * H;
    float* po = out + (size_t)t * H;
    for (int n = threadIdx.x; n < H; n += blockDim.x)
        po[n] = w0 * p0[n] + w1 * p1[n];
}

// ---------------- launch ------------------------------------------------------
extern "C" void kernel_launch(void* const* d_in, const int* in_sizes, int n_in,
                              void* d_out, int out_size) {
    const float* hidden = (const float*)d_in[0];
    const int*   eidx   = (const int*)d_in[1];
    const float* rw     = (const float*)d_in[2];
    const int*   gub    = (const int*)d_in[3];
    const int*   gus    = (const int*)d_in[4];
    const float* gubias = (const float*)d_in[5];
    const int*   db     = (const int*)d_in[6];
    const int*   ds     = (const int*)d_in[7];
    const float* dbias  = (const float*)d_in[8];
    float* out = (float*)d_out;

    static bool attr_set = false;
    if (!attr_set) {
        cudaFuncSetAttribute(gemm_mma_kernel<true>,
                             cudaFuncAttributeMaxDynamicSharedMemorySize, SMEM_DYN);
        cudaFuncSetAttribute(gemm_mma_kernel<false>,
                             cudaFuncAttributeMaxDynamicSharedMemorySize, SMEM_DYN);
        attr_set = true;
    }

    build_lists_kernel<<<1, 256>>>(eidx);

    {   // qdq hidden -> bf16 (8 values/thread)
        qdq_hidden_kernel<<<(T * H / 8) / 256, 256>>>(hidden);
    }
    {   // GEMM1 + swiglu + fused act qdq (tensor cores)
        dim3 grid(R1 / BN, NA / BM, NEXP);        // (45, 16, 8)
        gemm_mma_kernel<true><<<grid, 256, SMEM_DYN>>>(gub, gus, gubias, R1);
    }
    {   // GEMM2 (tensor cores); 2880/128 = 22.5 -> 23 blocks with guarded tail
        dim3 grid((H + BN - 1) / BN, NA / BM, NEXP);   // (23, 16, 8)
        gemm_mma_kernel<false><<<grid, 256, SMEM_DYN>>>(db, ds, dbias, H);
    }
    combine_kernel<<<T, 256>>>(rw, out);
}

// round 15
// speedup vs baseline: 1.1082x; 1.1082x over previous
#include <cuda_runtime.h>
#include <cuda_bf16.h>
#include <cuda_fp8.h>
#include <cuda_fp16.h>
#include <math.h>
#include <stdint.h>

// Problem shape (fixed)
#define T 1024
#define H 2880
#define NI 2880
#define NEXP 8
#define R1 5760          // 2*I rows of gate_up
#define G 90             // K groups of 32
#define NA 2048          // T * topk

// GEMM tiles: BM=128, K-step 64. GEMM1: BN=64 (warp 32x32, qdq-aligned).
// GEMM2: BN=96 (warp 32x48) -- lower LDS bytes/MAC within the 128-reg budget.
#define BM 128
#define BK 64
#define CHUNKS 45                    // 2880 / 64
#define ASTRB 144                    // padded row stride bytes (128B + 16B pad)
#define A_BYTES (BM * ASTRB)         // 18432

// ---------------- scratch ---------------------------------------------------
__device__ __nv_bfloat16 g_xq[T * H];      // qdq'd hidden, bf16 (exact)
__device__ __nv_bfloat16 g_actb[NA * NI];  // qdq'd activations, bf16 (exact)
__device__ float         g_out2[NA * H];   // per-assignment outputs
__device__ int g_tok[NA], g_pair_row[NA], g_cnt[NEXP], g_off[NEXP];

// ---------------- expert grouping (deterministic) ---------------------------
__global__ void build_lists_kernel(const int* __restrict__ eidx) {
    __shared__ int se[NA];
    __shared__ int offs[NEXP];
    int tid = threadIdx.x;
    for (int i = tid; i < NA; i += 256) se[i] = eidx[i];
    __syncthreads();
    if (tid < NEXP) {
        int c = 0;
        for (int i = 0; i < NA; i++) c += (se[i] == tid);
        g_cnt[tid] = c;
    }
    __syncthreads();
    if (tid == 0) {
        int s = 0;
        for (int e = 0; e < NEXP; e++) { offs[e] = s; g_off[e] = s; s += g_cnt[e]; }
    }
    __syncthreads();
    if (tid < NEXP) {
        int pos = offs[tid];
        for (int i = 0; i < NA; i++) {
            if (se[i] == tid) {
                g_tok[pos] = i >> 1;
                g_pair_row[i] = pos;
                pos++;
            }
        }
    }
}

// ---------------- MXFP8 qdq helpers ------------------------------------------
__device__ __forceinline__ int ceil_log2(float a) {
    int k; float m = frexpf(a, &k);
    int ee = (m == 0.5f) ? (k - 1) : k;   // exact ceil(log2(a))
    return max(-127, min(128, ee));
}
__device__ __forceinline__ float qdq_one(float v, float inv, float scale) {
    __nv_fp8_storage_t q = __nv_cvt_float_to_fp8(v * inv, __NV_SATFINITE, __NV_E4M3);
    __half_raw hr = __nv_cvt_fp8_to_halfraw(q, __NV_E4M3);
    return __half2float(*(__half*)&hr) * scale;
}

// Vectorized hidden qdq: 8 values/thread, 4 threads per 32-block.
__global__ void qdq_hidden_kernel(const float* __restrict__ in) {
    int gid = blockIdx.x * blockDim.x + threadIdx.x;   // T*H/8 threads
    size_t idx = (size_t)gid * 8;
    float4 v0 = *(const float4*)(in + idx);
    float4 v1 = *(const float4*)(in + idx + 4);
    float f[8] = {v0.x, v0.y, v0.z, v0.w, v1.x, v1.y, v1.z, v1.w};
    float a = 0.0f;
#pragma unroll
    for (int j = 0; j < 8; j++) a = fmaxf(a, fabsf(f[j]));
    a = fmaxf(a, __shfl_xor_sync(0xffffffffu, a, 1));
    a = fmaxf(a, __shfl_xor_sync(0xffffffffu, a, 2));
    a = fmaxf(a, 1e-12f);
    int ee = ceil_log2(a);
    float inv = ldexpf(1.0f, -ee);
    float scale = ldexpf(1.0f, ee);
    __nv_bfloat16 o[8];
#pragma unroll
    for (int j = 0; j < 8; j++) o[j] = __float2bfloat16(qdq_one(f[j], inv, scale));
    *(uint4*)(g_xq + idx) = *(uint4*)o;
}

// ---------------- low-level helpers -----------------------------------------
__device__ __forceinline__ void ldsm_x4(uint32_t* r, uint32_t addr) {
    asm volatile("ldmatrix.sync.aligned.m8n8.x4.shared.b16 {%0,%1,%2,%3}, [%4];\n"
                 : "=r"(r[0]), "=r"(r[1]), "=r"(r[2]), "=r"(r[3]) : "r"(addr));
}
__device__ __forceinline__ void mma16816(float* d, const uint32_t* a,
                                         uint32_t b0, uint32_t b1) {
    asm volatile(
        "mma.sync.aligned.m16n8k16.row.col.f32.bf16.bf16.f32 "
        "{%0,%1,%2,%3}, {%4,%5,%6,%7}, {%8,%9}, {%0,%1,%2,%3};\n"
        : "+f"(d[0]), "+f"(d[1]), "+f"(d[2]), "+f"(d[3])
        : "r"(a[0]), "r"(a[1]), "r"(a[2]), "r"(a[3]), "r"(b0), "r"(b1));
}
__device__ __forceinline__ uint32_t mulbf2(uint32_t a, uint32_t b) {
    uint32_t d;
    asm("mul.rn.bf16x2 %0, %1, %2;\n" : "=r"(d) : "r"(a), "r"(b));
    return d;
}

// PRMT-based fp4 dequant (verified R10-R14): 4 int32 (one packed byte each) +
// E8M0 scale -> 4 x bf16x2 in k-order. Exact in bf16.
__device__ __forceinline__ void dequant8(int4 v, int sval, uint32_t* out) {
    uint32_t c1 = __byte_perm((uint32_t)v.x, (uint32_t)v.y, 0x0040);
    uint32_t c2 = __byte_perm((uint32_t)v.z, (uint32_t)v.w, 0x4000);
    uint32_t comb = __byte_perm(c1, c2, 0x7610);   // [b(x),b(y),b(z),b(w)]
    uint32_t chn = comb >> 4;
    uint32_t xl = comb & 0x07070707u;
    uint32_t xh = chn & 0x07070707u;
    uint32_t sgl = (comb & 0x08080808u) << 4;
    uint32_t sgh = (chn & 0x08080808u) << 4;
    uint32_t yl = xl | (xl >> 4);
    uint32_t yh = xh | (xh >> 4);
    uint32_t sel_l = __byte_perm(yl, yl, 0x0020);
    uint32_t sel_h = __byte_perm(yh, yh, 0x0020);
    uint32_t hbLo = __byte_perm(0x3F3F3F00u, 0x40404040u, sel_l) | sgl;
    uint32_t lbLo = __byte_perm(0xC0800000u, 0xC0804000u, sel_l);
    uint32_t hbHi = __byte_perm(0x3F3F3F00u, 0x40404040u, sel_h) | sgh;
    uint32_t lbHi = __byte_perm(0xC0800000u, 0xC0804000u, sel_h);
    uint32_t M0 = __byte_perm(lbLo, hbLo, 0x5140);
    uint32_t M1 = __byte_perm(lbLo, hbLo, 0x7362);
    uint32_t N0 = __byte_perm(lbHi, hbHi, 0x5140);
    uint32_t N1 = __byte_perm(lbHi, hbHi, 0x7362);
    uint32_t sb = ((uint32_t)sval) << 7;
    sb |= sb << 16;
    out[0] = mulbf2(__byte_perm(M0, N0, 0x5410), sb);
    out[1] = mulbf2(__byte_perm(M0, N0, 0x7632), sb);
    out[2] = mulbf2(__byte_perm(M1, N1, 0x5410), sb);
    out[3] = mulbf2(__byte_perm(M1, N1, 0x7632), sb);
}

// ---------------- tensor-core GEMM (both stages) -----------------------------
// GEMM1: C[128,64], 8 warps 32x32, fused swiglu + act MXFP8-qdq (proven 768.9
// config). GEMM2: C[128,96], 8 warps 32x48 (acc=48 regs, no spill).
// Both: 2-stage smem double buffer, LDG register prefetch, one barrier/chunk.
template <bool IS_G1>
__global__ __launch_bounds__(256, 2) void gemm_mma_kernel(
    const int* __restrict__ wblocks, const int* __restrict__ wscales,
    const float* __restrict__ wbias, int NR) {
    constexpr int BNk = IS_G1 ? 64 : 96;
    constexpr int WN = IS_G1 ? 32 : 48;          // warp n-extent
    constexpr int NT = WN / 16;                  // B n16-tiles per warp (2 / 3)
    constexpr int NB = IS_G1 ? 2 : 4;            // raw int4 per thread per chunk
    constexpr int B_BYTESk = BNk * ASTRB;
    constexpr int STAGEk = A_BYTES + B_BYTESk;

    extern __shared__ char dsmem[];
    int e = blockIdx.z;
    int cnt = g_cnt[e];
    int m0 = blockIdx.y * BM;
    if (m0 >= cnt) return;
    int off = g_off[e];
    int nt = blockIdx.x;
    int tid = threadIdx.x;

    uint32_t sbase = (uint32_t)__cvta_generic_to_shared(dsmem);
    uint32_t abase = (sbase + 1023) & ~1023u;
    uint32_t st_u[2] = {abase, abase + (uint32_t)STAGEk};

    // --- A mapping: 2 threads per row, 64B (32 bf16) each ---
    int a_m = tid >> 1;
    int a_half = tid & 1;
    int arow = min(m0 + a_m, cnt - 1);   // clamp; garbage rows never stored out
    const __nv_bfloat16* aptr;
    if (IS_G1) {
        aptr = g_xq + (size_t)g_tok[off + arow] * H + a_half * 32;
    } else {
        aptr = g_actb + (size_t)(off + arow) * NI + a_half * 32;
    }
    // --- B mapping ---
    // GEMM1: 4 threads/row, each owns int4 slot b_sel of both k32 groups.
    // GEMM2: 2 threads/row (192 active), each owns one full k32 group (4 int4).
    int b_n, b_sel;
    bool bwork;
    if (IS_G1) { b_n = tid >> 2; b_sel = tid & 3; bwork = true; }
    else       { b_n = tid >> 1; b_sel = tid & 1; bwork = (tid < 2 * BNk); }
    size_t wrow = (size_t)e * NR + nt * BNk + (bwork ? b_n : 0);
    const int* bptr = wblocks + wrow * (G * 16);
    const int* sptr = wscales + wrow * G;

    uint32_t a_dst = (uint32_t)a_m * ASTRB + a_half * 64;            // bytes
    uint32_t b_dst = A_BYTES + (uint32_t)b_n * ASTRB +
                     (IS_G1 ? (uint32_t)b_sel * 16 : (uint32_t)b_sel * 64);

    // per-warp ldmatrix offsets (within a stage)
    int wid = tid >> 5, lane = tid & 31;
    int wm = (wid & 3) * 32;
    int wn = (wid >> 2) * WN;
    uint32_t aA_off = (uint32_t)(wm + (lane & 15)) * ASTRB + (lane >> 4) * 16;
    uint32_t aB_off = A_BYTES + (uint32_t)(wn + (lane & 15)) * ASTRB +
                      (lane >> 4) * 16;

    float acc[2][2 * NT][4];
#pragma unroll
    for (int i = 0; i < 2; i++)
#pragma unroll
        for (int j = 0; j < 2 * NT; j++)
#pragma unroll
            for (int c = 0; c < 4; c++) acc[i][j][c] = 0.0f;

    // ---- B load/store helpers (by config) ----
    auto load_b = [&](int c, int4* bv, int* sv) {
        if (IS_G1) {
            bv[0] = *(const int4*)(bptr + (size_t)(2 * c) * 16 + b_sel * 4);
            bv[1] = *(const int4*)(bptr + (size_t)(2 * c + 1) * 16 + b_sel * 4);
            sv[0] = sptr[2 * c];
            sv[1] = sptr[2 * c + 1];
        } else if (bwork) {
            const int* bp = bptr + (size_t)(2 * c + b_sel) * 16;
#pragma unroll
            for (int j = 0; j < 4; j++) bv[j] = *(const int4*)(bp + j * 4);
            sv[0] = sptr[2 * c + b_sel];
        }
    };
    auto store_b = [&](uint32_t stage, const int4* bv, const int* sv) {
        if (IS_G1) {
            uint32_t o[4];
            dequant8(bv[0], sv[0], o);
            asm volatile("st.shared.v4.b32 [%0], {%1,%2,%3,%4};"
                         :: "r"(stage + b_dst), "r"(o[0]), "r"(o[1]), "r"(o[2]), "r"(o[3]));
            dequant8(bv[1], sv[1], o);
            asm volatile("st.shared.v4.b32 [%0], {%1,%2,%3,%4};"
                         :: "r"(stage + b_dst + 64), "r"(o[0]), "r"(o[1]), "r"(o[2]), "r"(o[3]));
        } else if (bwork) {
#pragma unroll
            for (int j = 0; j < 4; j++) {
                uint32_t o[4];
                dequant8(bv[j], sv[0], o);
                asm volatile("st.shared.v4.b32 [%0], {%1,%2,%3,%4};"
                             :: "r"(stage + b_dst + j * 16),
                                "r"(o[0]), "r"(o[1]), "r"(o[2]), "r"(o[3]));
            }
        }
    };

    // ---- prologue: load + store chunk 0 into stage 0 ----
    {
        uint4 av[4];
#pragma unroll
        for (int j = 0; j < 4; j++) av[j] = *(const uint4*)(aptr + j * 8);
        int4 bv[NB]; int sv[2];
        load_b(0, bv, sv);
        uint32_t d = st_u[0] + a_dst;
#pragma unroll
        for (int j = 0; j < 4; j++)
            asm volatile("st.shared.v4.b32 [%0], {%1,%2,%3,%4};"
                         :: "r"(d + j * 16),
                            "r"(av[j].x), "r"(av[j].y), "r"(av[j].z), "r"(av[j].w));
        store_b(st_u[0], bv, sv);
    }

    for (int c = 0; c < CHUNKS; ++c) {
        // issue next chunk's global loads first (covered by compute below)
        uint4 avn[4]; int4 bvn[NB]; int svn[2];
        bool have_next = (c + 1 < CHUNKS);
        if (have_next) {
            const __nv_bfloat16* ap = aptr + (size_t)(c + 1) * BK;
#pragma unroll
            for (int j = 0; j < 4; j++) avn[j] = *(const uint4*)(ap + j * 8);
            load_b(c + 1, bvn, svn);
        }
        __syncthreads();   // stage c&1 stores (iter c-1 / prologue) visible
        // compute chunk c from stage c&1 (4 K16 steps)
        uint32_t aA = st_u[c & 1] + aA_off;
        uint32_t aB = st_u[c & 1] + aB_off;
#pragma unroll
        for (int ss = 0; ss < 4; ss++) {
            uint32_t A0[4], A1[4];
            ldsm_x4(A0, aA + ss * 32);
            ldsm_x4(A1, aA + 16 * ASTRB + ss * 32);
#pragma unroll
            for (int t = 0; t < NT; t++) {
                uint32_t Bt[4];
                ldsm_x4(Bt, aB + t * 16 * ASTRB + ss * 32);
                mma16816(acc[0][2 * t + 0], A0, Bt[0], Bt[2]);
                mma16816(acc[0][2 * t + 1], A0, Bt[1], Bt[3]);
                mma16816(acc[1][2 * t + 0], A1, Bt[0], Bt[2]);
                mma16816(acc[1][2 * t + 1], A1, Bt[1], Bt[3]);
            }
        }
        // store chunk c+1 into stage (c+1)&1 (readers finished in iter c-1)
        if (have_next) {
            uint32_t d = st_u[(c + 1) & 1] + a_dst;
#pragma unroll
            for (int j = 0; j < 4; j++)
                asm volatile("st.shared.v4.b32 [%0], {%1,%2,%3,%4};"
                             :: "r"(d + j * 16),
                                "r"(avn[j].x), "r"(avn[j].y), "r"(avn[j].z), "r"(avn[j].w));
            store_b(st_u[(c + 1) & 1], bvn, svn);
        }
    }

    // ---------------- epilogue ----------------
    int lm = lane >> 2;
    int lc = (lane & 3) * 2;
    if (IS_G1) {
        // swiglu -> fp32 act, fused MXFP8 qdq -> bf16 g_actb. One 32-act block
        // per CTA-row (BN=64); rmax via 4-lane shfl + cross-warp-half smem.
        float av[2][2][4];             // [mi][rowpair][nf]
        float rmax[2][2] = {{0.f, 0.f}, {0.f, 0.f}};
#pragma unroll
        for (int mi = 0; mi < 2; mi++) {
#pragma unroll
            for (int nf = 0; nf < 4; nf++) {
                int col = nt * BNk + wn + nf * 8 + lc;
                float be = wbias[e * R1 + col];
                float bo = wbias[e * R1 + col + 1];
                {
                    float gate = fminf(acc[mi][nf][0] + be, 7.0f);
                    float up = fminf(fmaxf(acc[mi][nf][1] + bo, -7.0f), 7.0f);
                    float glu = gate / (1.0f + expf(-1.702f * gate));
                    float a0 = (up + 1.0f) * glu;
                    av[mi][0][nf] = a0;
                    rmax[mi][0] = fmaxf(rmax[mi][0], fabsf(a0));
                }
                {
                    float gate = fminf(acc[mi][nf][2] + be, 7.0f);
                    float up = fminf(fmaxf(acc[mi][nf][3] + bo, -7.0f), 7.0f);
                    float glu = gate / (1.0f + expf(-1.702f * gate));
                    float a1 = (up + 1.0f) * glu;
                    av[mi][1][nf] = a1;
                    rmax[mi][1] = fmaxf(rmax[mi][1], fabsf(a1));
                }
            }
        }
#pragma unroll
        for (int mi = 0; mi < 2; mi++)
#pragma unroll
            for (int p = 0; p < 2; p++) {
                rmax[mi][p] = fmaxf(rmax[mi][p],
                                    __shfl_xor_sync(0xffffffffu, rmax[mi][p], 1));
                rmax[mi][p] = fmaxf(rmax[mi][p],
                                    __shfl_xor_sync(0xffffffffu, rmax[mi][p], 2));
            }
        // cross-warp (two n-halves) exchange via smem
        __syncthreads();                      // ring reads done; reuse as float buf
        float* smax = (float*)dsmem;
        int half = wid >> 2;
        if ((lane & 3) == 0) {
#pragma unroll
            for (int mi = 0; mi < 2; mi++)
#pragma unroll
                for (int p = 0; p < 2; p++)
                    smax[half * 128 + wm + mi * 16 + p * 8 + lm] = rmax[mi][p];
        }
        __syncthreads();
#pragma unroll
        for (int mi = 0; mi < 2; mi++) {
#pragma unroll
            for (int p = 0; p < 2; p++) {
                int rloc = wm + mi * 16 + p * 8 + lm;
                int rbase = m0 + rloc;
                float bm = fmaxf(fmaxf(rmax[mi][p], smax[(1 ^ half) * 128 + rloc]),
                                 1e-12f);
                int ee = ceil_log2(bm);
                float inv = ldexpf(1.0f, -ee);
                float scale = ldexpf(1.0f, ee);
                if (rbase < cnt) {
                    __nv_bfloat16* dst = g_actb + (size_t)(off + rbase) * NI +
                                         nt * 32 + (wn >> 1) + (lane & 3);
#pragma unroll
                    for (int nf = 0; nf < 4; nf++)
                        dst[nf * 4] = __float2bfloat16(qdq_one(av[mi][p][nf], inv, scale));
                }
            }
        }
    } else {
#pragma unroll
        for (int mi = 0; mi < 2; mi++) {
#pragma unroll
            for (int nj = 0; nj < 2 * NT; nj++) {
                int col = nt * BNk + wn + nj * 8 + lc;
                int rbase = m0 + wm + mi * 16 + lm;
                float b0 = wbias[e * H + col];
                float b1 = wbias[e * H + col + 1];
                if (rbase < cnt) {
                    float2 r = make_float2(acc[mi][nj][0] + b0, acc[mi][nj][1] + b1);
                    *(float2*)(g_out2 + (size_t)(off + rbase) * H + col) = r;
                }
                if (rbase + 8 < cnt) {
                    float2 r = make_float2(acc[mi][nj][2] + b0, acc[mi][nj][3] + b1);
                    *(float2*)(g_out2 + (size_t)(off + rbase + 8) * H + col) = r;
                }
            }
        }
    }
}

// ---------------- combine (deterministic) -----------------------------------
__global__ void combine_kernel(const float* __restrict__ rw,
                               float* __restrict__ out) {
    int t = blockIdx.x;
    int r0 = g_pair_row[t * 2 + 0];
    int r1 = g_pair_row[t * 2 + 1];
    float w0 = rw[t * 2 + 0];
    float w1 = rw[t * 2 + 1];
    const float* p0 = g_out2 + (size_t)r0 * H;
    const float* p1 = g_out2 + (size_t)r1 * H;
    float* po = out + (size_t)t * H;
    for (int n = threadIdx.x; n < H; n += blockDim.x)
        po[n] = w0 * p0[n] + w1 * p1[n];
}

// ---------------- launch ------------------------------------------------------
#define SMEM_G1 (1024 + 2 * (A_BYTES + 64 * ASTRB))    // 56320
#define SMEM_G2 (1024 + 2 * (A_BYTES + 96 * ASTRB))    // 65536

extern "C" void kernel_launch(void* const* d_in, const int* in_sizes, int n_in,
                              void* d_out, int out_size) {
    const float* hidden = (const float*)d_in[0];
    const int*   eidx   = (const int*)d_in[1];
    const float* rw     = (const float*)d_in[2];
    const int*   gub    = (const int*)d_in[3];
    const int*   gus    = (const int*)d_in[4];
    const float* gubias = (const float*)d_in[5];
    const int*   db     = (const int*)d_in[6];
    const int*   ds     = (const int*)d_in[7];
    const float* dbias  = (const float*)d_in[8];
    float* out = (float*)d_out;

    static bool attr_set = false;
    if (!attr_set) {
        cudaFuncSetAttribute(gemm_mma_kernel<true>,
                             cudaFuncAttributeMaxDynamicSharedMemorySize, SMEM_G1);
        cudaFuncSetAttribute(gemm_mma_kernel<false>,
                             cudaFuncAttributeMaxDynamicSharedMemorySize, SMEM_G2);
        attr_set = true;
    }

    build_lists_kernel<<<1, 256>>>(eidx);

    {   // qdq hidden -> bf16 (8 values/thread)
        qdq_hidden_kernel<<<(T * H / 8) / 256, 256>>>(hidden);
    }
    {   // GEMM1 + swiglu + fused act qdq (BN=64, proven config)
        dim3 grid(R1 / 64, NA / BM, NEXP);        // (90, 16, 8)
        gemm_mma_kernel<true><<<grid, 256, SMEM_G1>>>(gub, gus, gubias, R1);
    }
    {   // GEMM2 (BN=96; 2880/96 = 30 exact, no tail)
        dim3 grid(H / 96, NA / BM, NEXP);         // (30, 16, 8)
        gemm_mma_kernel<false><<<grid, 256, SMEM_G2>>>(db, ds, dbias, H);
    }
    combine_kernel<<<T, 256>>>(rw, out);
}